// round 6
// baseline (speedup 1.0000x reference)
#include <cuda_runtime.h>
#include <math.h>

#define NNODES 8192
#define KNBR   32

// ---------------- scratch (static device arrays; no allocation) ----------------
__device__ float g_proj [NNODES * 1152];      // q(192) | kv(384) | qp_raw(144) | kvp_raw(432)
__device__ float g_wcat [384 * 1152];
__device__ float g_bcat [1152];
__device__ float g_qpts [NNODES * 144];       // (H,PQ,3) transformed
__device__ float g_kvpts[NNODES * 432];       // (H,12,3) transformed
__device__ float g_bpair[NNODES * KNBR * 12]; // sqrt(1/3)*(z@w_b+b_b)
__device__ float g_pairz[NNODES * KNBR * 32]; // z@w_dz+b_dz
__device__ float g_cat  [NNODES * 960];

// ---------------- weight packing (split: big matrix / bias, for profile slotting) ----------------
__global__ void pack_w(const float* __restrict__ wq, const float* __restrict__ wkv,
                       const float* __restrict__ wqp, const float* __restrict__ wkvp)
{
    int t = blockIdx.x * blockDim.x + threadIdx.x;
    int stride = gridDim.x * blockDim.x;
    for (int i = t; i < 384 * 1152; i += stride) {
        int r = i / 1152, c = i % 1152;
        float v;
        if      (c < 192) v = wq  [r * 192 + c];
        else if (c < 576) v = wkv [r * 384 + (c - 192)];
        else if (c < 720) v = wqp [r * 144 + (c - 576)];
        else              v = wkvp[r * 432 + (c - 720)];
        g_wcat[i] = v;
    }
}
__global__ void pack_b(const float* __restrict__ bq, const float* __restrict__ bkv,
                       const float* __restrict__ bqp, const float* __restrict__ bkvp)
{
    int c = blockIdx.x * blockDim.x + threadIdx.x;
    if (c < 1152) {
        float v;
        if      (c < 192) v = bq [c];
        else if (c < 576) v = bkv[c - 192];
        else if (c < 720) v = bqp[c - 576];
        else              v = bkvp[c - 720];
        g_bcat[c] = v;
    }
}

// ---------------- fp32 SGEMM, double-buffered: C[M,N] = A[M,K]@B[K,N] + bias ----------------
template<int N, int K>
__device__ __forceinline__ void gemm_body(const float* __restrict__ A,
                                          const float* __restrict__ B,
                                          const float* __restrict__ bias,
                                          float* __restrict__ C)
{
    __shared__ float As[2][8][132];
    __shared__ float Bs[2][8][128];
    const int tid  = threadIdx.x;
    const int brow = blockIdx.y * 128;
    const int bcol = blockIdx.x * 128;
    const int arow = tid >> 1, acol = (tid & 1) * 4;
    const int bkr  = tid >> 5, bco  = (tid & 31) * 4;
    const int ty = tid >> 4, tx = tid & 15;

    float acc[8][8];
#pragma unroll
    for (int i = 0; i < 8; i++)
#pragma unroll
        for (int j = 0; j < 8; j++) acc[i][j] = 0.f;

    {
        float4 av = *(const float4*)(A + (size_t)(brow + arow) * K + acol);
        As[0][acol + 0][arow] = av.x;
        As[0][acol + 1][arow] = av.y;
        As[0][acol + 2][arow] = av.z;
        As[0][acol + 3][arow] = av.w;
        *(float4*)&Bs[0][bkr][bco] = *(const float4*)(B + (size_t)bkr * N + bcol + bco);
    }
    __syncthreads();

    int buf = 0;
    for (int k0 = 0; k0 < K; k0 += 8) {
        const bool more = (k0 + 8) < K;
        float4 av2, bv2;
        if (more) {
            av2 = *(const float4*)(A + (size_t)(brow + arow) * K + (k0 + 8) + acol);
            bv2 = *(const float4*)(B + (size_t)(k0 + 8 + bkr) * N + bcol + bco);
        }
#pragma unroll
        for (int kk = 0; kk < 8; kk++) {
            float ar[8], br[8];
#pragma unroll
            for (int i = 0; i < 8; i++) ar[i] = As[buf][kk][ty * 8 + i];
#pragma unroll
            for (int j = 0; j < 8; j++) br[j] = Bs[buf][kk][tx * 8 + j];
#pragma unroll
            for (int i = 0; i < 8; i++)
#pragma unroll
                for (int j = 0; j < 8; j++) acc[i][j] = fmaf(ar[i], br[j], acc[i][j]);
        }
        if (more) {
            As[buf ^ 1][acol + 0][arow] = av2.x;
            As[buf ^ 1][acol + 1][arow] = av2.y;
            As[buf ^ 1][acol + 2][arow] = av2.z;
            As[buf ^ 1][acol + 3][arow] = av2.w;
            *(float4*)&Bs[buf ^ 1][bkr][bco] = bv2;
            __syncthreads();
            buf ^= 1;
        }
    }
#pragma unroll
    for (int i = 0; i < 8; i++) {
        int r = brow + ty * 8 + i;
#pragma unroll
        for (int j = 0; j < 8; j++) {
            int c = bcol + tx * 8 + j;
            C[(size_t)r * N + c] = acc[i][j] + bias[c];
        }
    }
}

__global__ __launch_bounds__(256) void gemm_proj(const float* __restrict__ s)
{
    gemm_body<1152, 384>(s, g_wcat, g_bcat, g_proj);
}
__global__ __launch_bounds__(256) void gemm_out(const float* __restrict__ wout,
                                                const float* __restrict__ bout,
                                                float* __restrict__ out)
{
    gemm_body<384, 960>(g_cat, wout, bout, out);
}

// ---------------- rigid transform of qp/kvp points ----------------
__global__ __launch_bounds__(192) void transform_points(const float* __restrict__ rot,
                                                        const float* __restrict__ trans)
{
    int n = blockIdx.x;
    __shared__ float R[9], T[3];
    int t = threadIdx.x;
    if (t < 9) R[t] = rot[n * 9 + t];
    if (t < 3) T[t] = trans[n * 3 + t];
    __syncthreads();
    if (t < 48) {
        const float* base = g_proj + (size_t)n * 1152 + 576;
        float x = base[t], y = base[48 + t], z = base[96 + t];
        float* o = g_qpts + (size_t)n * 144 + t * 3;
        o[0] = fmaf(R[0], x, fmaf(R[1], y, fmaf(R[2], z, T[0])));
        o[1] = fmaf(R[3], x, fmaf(R[4], y, fmaf(R[5], z, T[1])));
        o[2] = fmaf(R[6], x, fmaf(R[7], y, fmaf(R[8], z, T[2])));
    } else {
        int j = t - 48;
        const float* base = g_proj + (size_t)n * 1152 + 720;
        float x = base[j], y = base[144 + j], z = base[288 + j];
        float* o = g_kvpts + (size_t)n * 432 + j * 3;
        o[0] = fmaf(R[0], x, fmaf(R[1], y, fmaf(R[2], z, T[0])));
        o[1] = fmaf(R[3], x, fmaf(R[4], y, fmaf(R[5], z, T[1])));
        o[2] = fmaf(R[6], x, fmaf(R[7], y, fmaf(R[8], z, T[2])));
    }
}

// ---------------- zproj v3: 2 threads per edge, 22(+2 pad) cols each ----------------
// Block: 256 threads = 128 edges. Even lane: cols 0..21; odd lane: cols 22..43.
// Both halves run IDENTICAL code (6x LDS.128 + 24 FMA per k) -> no divergence.
// Weight halves staged at smem offsets 0 / 776 floats (3104B = 32 mod 128 -> distinct banks).
#define ZEDGES 128
#define HOFF   776            // floats; 16B-aligned, bank-shifted vs half 0
__global__ __launch_bounds__(256) void zproj(const float* __restrict__ z,
                                             const float* __restrict__ wb,  const float* __restrict__ bb,
                                             const float* __restrict__ wdz, const float* __restrict__ bdz)
{
    __shared__ float sz[ZEDGES * 33];     // bank(e,k) = (e+k)%32 -> conflict-free scalar reads
    __shared__ float sw2[HOFF + 32 * 24]; // [half*HOFF + k*24 + c24], 22 real cols + 2 zero pad
    const int tid  = threadIdx.x;
    const int eloc = tid >> 1;
    const int half = tid & 1;
    const size_t e0 = (size_t)blockIdx.x * ZEDGES;

    float acc[24];
#pragma unroll
    for (int c = 0; c < 24; c++) acc[c] = 0.f;

    const int wbase = half * HOFF;

    for (int pass = 0; pass < 4; pass++) {
        if (pass) __syncthreads();
        // stage z chunk: 128 edges x 32 k, coalesced 128B per warp
#pragma unroll
        for (int idx = tid; idx < ZEDGES * 32; idx += 256) {
            int row = idx >> 5, k = idx & 31;
            sz[row * 33 + k] = z[(e0 + row) * 128 + pass * 32 + k];
        }
        // stage weights: both halves, 2*32*24 slots (col>=22 in each half -> 0)
        for (int i = tid; i < 2 * 32 * 24; i += 256) {
            int hh  = i / (32 * 24);
            int rem = i - hh * (32 * 24);
            int kk  = rem / 24, c24 = rem - kk * 24;
            int col = hh * 22 + c24;
            float v = 0.f;
            if (c24 < 22)
                v = (col < 12) ? wb[(pass * 32 + kk) * 12 + col]
                               : wdz[(pass * 32 + kk) * 32 + (col - 12)];
            sw2[hh * HOFF + kk * 24 + c24] = v;
        }
        __syncthreads();

#pragma unroll 4
        for (int k = 0; k < 32; k++) {
            float zv = sz[eloc * 33 + k];
            const float4* w4 = (const float4*)(sw2 + wbase + k * 24);
#pragma unroll
            for (int j = 0; j < 6; j++) {
                float4 w = w4[j];
                acc[4 * j + 0] = fmaf(zv, w.x, acc[4 * j + 0]);
                acc[4 * j + 1] = fmaf(zv, w.y, acc[4 * j + 1]);
                acc[4 * j + 2] = fmaf(zv, w.z, acc[4 * j + 2]);
                acc[4 * j + 3] = fmaf(zv, w.w, acc[4 * j + 3]);
            }
        }
    }

    // epilogue
    const size_t e = e0 + eloc;
    if (half == 0) {
        // cols 0..11 -> b_pair; cols 12..21 -> pairz[0..9]
        const float S = 0.5773502691896258f;  // sqrt(1/3)
        float tb[12];
#pragma unroll
        for (int c = 0; c < 12; c++) tb[c] = S * (acc[c] + __ldg(bb + c));
        float4* pb = (float4*)(g_bpair + e * 12);
#pragma unroll
        for (int i = 0; i < 3; i++)
            pb[i] = make_float4(tb[4 * i], tb[4 * i + 1], tb[4 * i + 2], tb[4 * i + 3]);
        float* pz = g_pairz + e * 32;
#pragma unroll
        for (int c = 0; c < 10; c++) pz[c] = acc[12 + c] + __ldg(bdz + c);
    } else {
        // cols 22..43 -> pairz[10..31]
        float* pz = g_pairz + e * 32;
#pragma unroll
        for (int c = 0; c < 22; c++) pz[10 + c] = acc[c] + __ldg(bdz + 10 + c);
    }
}

// ---------------- fused attention: logits + softmax + o / o_pt / o_pair ----------------
__global__ __launch_bounds__(384) void attn_kernel(const int* __restrict__ edge_index,
                                                   const float* __restrict__ rot,
                                                   const float* __restrict__ trans,
                                                   const float* __restrict__ mask,
                                                   const float* __restrict__ head_weights)
{
    int n = blockIdx.x;
    int t = threadIdx.x;
    __shared__ int   s_idx[32];
    __shared__ float s_mask[32];
    __shared__ float s_q[192];
    __shared__ float s_qp[144];
    __shared__ float s_R[9], s_T[3];
    __shared__ float s_hw[12];
    __shared__ float s_a[12][33];
    __shared__ float s_opt[288];
    __shared__ float s_pz[32][33];

    if (t < 32) {
        int nb = edge_index[n * 32 + t];
        s_idx[t]  = nb;
        s_mask[t] = mask[nb];
    }
    if (t >= 32 && t < 224)  s_q [t - 32]  = g_proj[(size_t)n * 1152 + (t - 32)];
    if (t >= 224 && t < 368) s_qp[t - 224] = g_qpts[(size_t)n * 144 + (t - 224)];
    if (t >= 368 && t < 377) s_R [t - 368] = rot  [n * 9 + (t - 368)];
    if (t >= 377 && t < 380) s_T [t - 377] = trans[n * 3 + (t - 377)];
    if (t < 12) {
        float x = head_weights[t];
        float sp = (x > 20.f) ? x : log1pf(expf(x));
        s_hw[t] = sp * 0.13608276348795434f;   // softplus * sqrt(1/54)
    }
    __syncthreads();

    {
        int h = t >> 5, k = t & 31;
        int nb = s_idx[k];
        const float* kg = g_proj + (size_t)nb * 1152 + 192 + h * 32;
        float dot = 0.f;
#pragma unroll
        for (int c = 0; c < 16; c++) dot = fmaf(s_q[h * 16 + c], kg[c], dot);
        const float* kp = g_kvpts + (size_t)nb * 432 + h * 36;
        float pt = 0.f;
#pragma unroll
        for (int pi = 0; pi < 12; pi++) {
            float d = s_qp[h * 12 + pi] - kp[pi];
            pt = fmaf(d, d, pt);
        }
        float logit = dot * 0.14433756729740643f
                    + g_bpair[((size_t)n * 32 + k) * 12 + h]
                    - 0.5f * s_hw[h] * pt
                    + 100000.0f * (s_mask[k] - 1.0f);
        float m = logit;
#pragma unroll
        for (int o = 16; o; o >>= 1) m = fmaxf(m, __shfl_xor_sync(0xffffffffu, m, o));
        float e = expf(logit - m);
        float ssum = e;
#pragma unroll
        for (int o = 16; o; o >>= 1) ssum += __shfl_xor_sync(0xffffffffu, ssum, o);
        s_a[h][k] = e / ssum;
    }
    for (int i = t; i < 32 * 32; i += 384)
        s_pz[i >> 5][i & 31] = g_pairz[((size_t)n * 32 + (i >> 5)) * 32 + (i & 31)];
    __syncthreads();

    float* catn = g_cat + (size_t)n * 960;

    if (t < 192) {
        int h = t >> 4, c = t & 15;
        float acc = 0.f;
#pragma unroll 4
        for (int k = 0; k < 32; k++)
            acc = fmaf(s_a[h][k], g_proj[(size_t)s_idx[k] * 1152 + 192 + h * 32 + 16 + c], acc);
        catn[h * 16 + c] = acc;
    }
    if (t < 288) {
        int j = t / 3, i = t - j * 3;
        int h = j >> 3, p = j & 7;
        float acc = 0.f;
#pragma unroll 4
        for (int k = 0; k < 32; k++)
            acc = fmaf(s_a[h][k], g_kvpts[(size_t)s_idx[k] * 432 + h * 36 + (4 + p) * 3 + i], acc);
        s_opt[t] = acc;
    }
    {
        int h = t >> 5, c = t & 31;
        float acc = 0.f;
#pragma unroll
        for (int k = 0; k < 32; k++)
            acc = fmaf(s_a[h][k], s_pz[k][c], acc);
        catn[576 + h * 32 + c] = acc;
    }
    __syncthreads();
    if (t < 96) {
        float gx = s_opt[t * 3 + 0] - s_T[0];
        float gy = s_opt[t * 3 + 1] - s_T[1];
        float gz = s_opt[t * 3 + 2] - s_T[2];
        float lx = fmaf(s_R[0], gx, fmaf(s_R[3], gy, s_R[6] * gz));
        float ly = fmaf(s_R[1], gx, fmaf(s_R[4], gy, s_R[7] * gz));
        float lz = fmaf(s_R[2], gx, fmaf(s_R[5], gy, s_R[8] * gz));
        catn[192 + t] = lx;
        catn[288 + t] = ly;
        catn[384 + t] = lz;
        catn[480 + t] = sqrtf(fmaf(lx, lx, fmaf(ly, ly, fmaf(lz, lz, 1e-8f))));
    }
}

// ---------------- launch ----------------
// Order puts gemm_proj in slot 4 (the slot ncu captures) for next-round visibility.
extern "C" void kernel_launch(void* const* d_in, const int* in_sizes, int n_in,
                              void* d_out, int out_size)
{
    const float* s     = (const float*)d_in[0];
    const float* z     = (const float*)d_in[1];
    const int*   ei    = (const int*)  d_in[2];
    const float* rot   = (const float*)d_in[3];
    const float* trans = (const float*)d_in[4];
    const float* mask  = (const float*)d_in[5];
    const float* w_q   = (const float*)d_in[6];
    const float* b_q   = (const float*)d_in[7];
    const float* w_kv  = (const float*)d_in[8];
    const float* b_kv  = (const float*)d_in[9];
    const float* w_qp  = (const float*)d_in[10];
    const float* b_qp  = (const float*)d_in[11];
    const float* w_kvp = (const float*)d_in[12];
    const float* b_kvp = (const float*)d_in[13];
    const float* w_b   = (const float*)d_in[14];
    const float* b_b   = (const float*)d_in[15];
    const float* w_dz  = (const float*)d_in[16];
    const float* b_dz  = (const float*)d_in[17];
    const float* hw    = (const float*)d_in[18];
    const float* w_out = (const float*)d_in[19];
    const float* b_out = (const float*)d_in[20];
    float* out = (float*)d_out;

    zproj<<<(NNODES * KNBR) / ZEDGES, 256>>>(z, w_b, b_b, w_dz, b_dz);   // slot 1
    pack_w<<<256, 256>>>(w_q, w_kv, w_qp, w_kvp);                        // slot 2
    pack_b<<<5, 256>>>(b_q, b_kv, b_qp, b_kvp);                          // slot 3
    gemm_proj<<<dim3(1152 / 128, NNODES / 128), 256>>>(s);               // slot 4 (profiled)
    transform_points<<<NNODES, 192>>>(rot, trans);                       // slot 5
    attn_kernel<<<NNODES, 384>>>(ei, rot, trans, mask, hw);              // slot 6
    gemm_out<<<dim3(384 / 128, NNODES / 128), 256>>>(w_out, b_out, out); // slot 7
}

// round 7
// speedup vs baseline: 1.7934x; 1.7934x over previous
#include <cuda_runtime.h>
#include <cuda_bf16.h>
#include <math.h>

#define NNODES 8192
#define KNBR   32

// ---------------- scratch (static device arrays; no allocation) ----------------
__device__ __align__(16) float g_proj [NNODES * 1152];   // q(192)|kv(384)|qp(144)|kvp(432)
__device__ __align__(16) float g_bcat [1152];
__device__ __align__(16) float g_qpts [NNODES * 144];
__device__ __align__(16) float g_kvpts[NNODES * 432];
__device__ __align__(16) float g_bpair[NNODES * KNBR * 12];
__device__ __align__(16) float g_pairz[NNODES * KNBR * 32];
// bf16 hi/lo split operands for tensor-core GEMMs
__device__ __align__(16) __nv_bfloat16 g_sh   [NNODES * 384];
__device__ __align__(16) __nv_bfloat16 g_sl   [NNODES * 384];
__device__ __align__(16) __nv_bfloat16 g_wcath[384 * 1152];
__device__ __align__(16) __nv_bfloat16 g_wcatl[384 * 1152];
__device__ __align__(16) __nv_bfloat16 g_wouth[960 * 384];
__device__ __align__(16) __nv_bfloat16 g_woutl[960 * 384];
__device__ __align__(16) __nv_bfloat16 g_cath [NNODES * 960];
__device__ __align__(16) __nv_bfloat16 g_catl [NNODES * 960];

// ---------------- helpers ----------------
__device__ __forceinline__ void split_store(__nv_bfloat16* ph, __nv_bfloat16* pl, float x)
{
    __nv_bfloat16 h = __float2bfloat16(x);
    *ph = h;
    *pl = __float2bfloat16(x - __bfloat162float(h));
}

__device__ __forceinline__ void mma_bf16(float* c, const unsigned* a, const unsigned* b)
{
    asm volatile(
        "mma.sync.aligned.m16n8k16.row.col.f32.bf16.bf16.f32 "
        "{%0,%1,%2,%3}, {%4,%5,%6,%7}, {%8,%9}, {%0,%1,%2,%3};"
        : "+f"(c[0]), "+f"(c[1]), "+f"(c[2]), "+f"(c[3])
        : "r"(a[0]), "r"(a[1]), "r"(a[2]), "r"(a[3]), "r"(b[0]), "r"(b[1]));
}
__device__ __forceinline__ void ldsm_x4(unsigned* d, unsigned addr)
{
    asm volatile("ldmatrix.sync.aligned.m8n8.x4.shared.b16 {%0,%1,%2,%3}, [%4];"
                 : "=r"(d[0]), "=r"(d[1]), "=r"(d[2]), "=r"(d[3]) : "r"(addr));
}
__device__ __forceinline__ void ldsm_x2t(unsigned* d, unsigned addr)
{
    asm volatile("ldmatrix.sync.aligned.m8n8.x2.trans.shared.b16 {%0,%1}, [%2];"
                 : "=r"(d[0]), "=r"(d[1]) : "r"(addr));
}

// ---------------- converters / packers ----------------
__global__ void cvt_s(const float4* __restrict__ s)   // grid covers NNODES*384/4
{
    int i = blockIdx.x * blockDim.x + threadIdx.x;
    float4 v = s[i];
    __nv_bfloat16* ph = g_sh + i * 4;
    __nv_bfloat16* pl = g_sl + i * 4;
    split_store(ph + 0, pl + 0, v.x);
    split_store(ph + 1, pl + 1, v.y);
    split_store(ph + 2, pl + 2, v.z);
    split_store(ph + 3, pl + 3, v.w);
}

__global__ void pack_w(const float* __restrict__ wq, const float* __restrict__ wkv,
                       const float* __restrict__ wqp, const float* __restrict__ wkvp)
{
    int t = blockIdx.x * blockDim.x + threadIdx.x;
    int stride = gridDim.x * blockDim.x;
    for (int i = t; i < 384 * 1152; i += stride) {
        int r = i / 1152, c = i % 1152;
        float v;
        if      (c < 192) v = wq  [r * 192 + c];
        else if (c < 576) v = wkv [r * 384 + (c - 192)];
        else if (c < 720) v = wqp [r * 144 + (c - 576)];
        else              v = wkvp[r * 432 + (c - 720)];
        split_store(g_wcath + i, g_wcatl + i, v);
    }
}

__global__ void prep_small(const float* __restrict__ bq, const float* __restrict__ bkv,
                           const float* __restrict__ bqp, const float* __restrict__ bkvp,
                           const float* __restrict__ wout)
{
    int i = blockIdx.x * blockDim.x + threadIdx.x;
    if (i < 1152) {
        float v;
        if      (i < 192) v = bq [i];
        else if (i < 576) v = bkv[i - 192];
        else if (i < 720) v = bqp[i - 576];
        else              v = bkvp[i - 720];
        g_bcat[i] = v;
    }
    if (i < 960 * 384)
        split_store(g_wouth + i, g_woutl + i, wout[i]);
}

// ---------------- bf16 hi/lo compensated tensor-core GEMM ----------------
// C[M,N] = A[M,K]@B[K,N] + bias, computed as Ah*Bh + Ah*Bl + Al*Bh (fp32 accum).
// Block tile 128x64, 256 threads (8 warps, 2x4), warp tile 64x16, K-chunk 32.
#define BM 128
#define BN 64
#define KC 32
template<int K>
__device__ __forceinline__ void mma_gemm_body(
    const __nv_bfloat16* __restrict__ Ah, const __nv_bfloat16* __restrict__ Al,
    const __nv_bfloat16* __restrict__ Bh, const __nv_bfloat16* __restrict__ Bl,
    const float* __restrict__ bias, float* __restrict__ C, const int N)
{
    __shared__ __nv_bfloat16 sAh[BM * 40], sAl[BM * 40];   // row pitch 40 (80B) -> LDSM conflict-free
    __shared__ __nv_bfloat16 sBh[KC * 72], sBl[KC * 72];   // row pitch 72 (144B)

    const int tid  = threadIdx.x;
    const int lane = tid & 31, warp = tid >> 5;
    const int wm = warp >> 2, wn = warp & 3;               // 2 x 4 warp grid
    const long brow = (long)blockIdx.y * BM;
    const long bcol = (long)blockIdx.x * BN;

    float acc[4][2][4];
#pragma unroll
    for (int mi = 0; mi < 4; mi++)
#pragma unroll
        for (int ni = 0; ni < 2; ni++)
#pragma unroll
            for (int r = 0; r < 4; r++) acc[mi][ni][r] = 0.f;

    const int arow  = tid >> 1, apart = (tid & 1) * 16;    // A: 128 rows x 32 cols, 16 bf16/thread
    const int bkr   = tid >> 3, bnp   = (tid & 7) * 8;     // B: 32 rows x 64 cols,  8 bf16/thread

    const unsigned sAh_u = (unsigned)__cvta_generic_to_shared(sAh);
    const unsigned sAl_u = (unsigned)__cvta_generic_to_shared(sAl);
    const unsigned sBh_u = (unsigned)__cvta_generic_to_shared(sBh);
    const unsigned sBl_u = (unsigned)__cvta_generic_to_shared(sBl);

    // prologue: stage chunk 0 in registers
    uint4 rah0, rah1, ral0, ral1, rbh, rbl;
    {
        const size_t aoff = (size_t)(brow + arow) * K + apart;
        rah0 = *(const uint4*)(Ah + aoff); rah1 = *(const uint4*)(Ah + aoff + 8);
        ral0 = *(const uint4*)(Al + aoff); ral1 = *(const uint4*)(Al + aoff + 8);
        const size_t boff = (size_t)bkr * N + bcol + bnp;
        rbh = *(const uint4*)(Bh + boff);
        rbl = *(const uint4*)(Bl + boff);
    }

    for (int kc = 0; kc < K; kc += KC) {
        // commit staged chunk to smem
        *(uint4*)(sAh + arow * 40 + apart)     = rah0;
        *(uint4*)(sAh + arow * 40 + apart + 8) = rah1;
        *(uint4*)(sAl + arow * 40 + apart)     = ral0;
        *(uint4*)(sAl + arow * 40 + apart + 8) = ral1;
        *(uint4*)(sBh + bkr * 72 + bnp) = rbh;
        *(uint4*)(sBl + bkr * 72 + bnp) = rbl;
        __syncthreads();

        const bool more = (kc + KC) < K;
        if (more) {
            const size_t aoff = (size_t)(brow + arow) * K + kc + KC + apart;
            rah0 = *(const uint4*)(Ah + aoff); rah1 = *(const uint4*)(Ah + aoff + 8);
            ral0 = *(const uint4*)(Al + aoff); ral1 = *(const uint4*)(Al + aoff + 8);
            const size_t boff = (size_t)(kc + KC + bkr) * N + bcol + bnp;
            rbh = *(const uint4*)(Bh + boff);
            rbl = *(const uint4*)(Bl + boff);
        }

#pragma unroll
        for (int ks = 0; ks < 2; ks++) {
            const int kk = ks * 16;
            unsigned afh[4][4], afl[4][4];
            const int g = lane >> 3, r = lane & 7;
#pragma unroll
            for (int mi = 0; mi < 4; mi++) {
                const int row = wm * 64 + mi * 16 + (g & 1) * 8 + r;
                const int col = kk + (g >> 1) * 8;
                ldsm_x4(afh[mi], sAh_u + (unsigned)(row * 40 + col) * 2u);
                ldsm_x4(afl[mi], sAl_u + (unsigned)(row * 40 + col) * 2u);
            }
            unsigned bfh[2][2], bfl[2][2];
            const int g2 = (lane >> 3) & 1, r2 = lane & 7;
#pragma unroll
            for (int ni = 0; ni < 2; ni++) {
                const int krow = kk + g2 * 8 + r2;
                const int col  = wn * 16 + ni * 8;
                ldsm_x2t(bfh[ni], sBh_u + (unsigned)(krow * 72 + col) * 2u);
                ldsm_x2t(bfl[ni], sBl_u + (unsigned)(krow * 72 + col) * 2u);
            }
#pragma unroll
            for (int mi = 0; mi < 4; mi++)
#pragma unroll
                for (int ni = 0; ni < 2; ni++) {
                    mma_bf16(acc[mi][ni], afh[mi], bfh[ni]);   // Ah*Bh
                    mma_bf16(acc[mi][ni], afh[mi], bfl[ni]);   // Ah*Bl
                    mma_bf16(acc[mi][ni], afl[mi], bfh[ni]);   // Al*Bh
                }
        }
        if (more) __syncthreads();
    }

    // epilogue: frag -> global, +bias, float2 stores
    const int gr = lane >> 2, gc = (lane & 3) * 2;
#pragma unroll
    for (int mi = 0; mi < 4; mi++) {
        const long row0 = brow + wm * 64 + mi * 16 + gr;
#pragma unroll
        for (int ni = 0; ni < 2; ni++) {
            const long col0 = bcol + wn * 16 + ni * 8 + gc;
            const float b0 = bias[col0], b1 = bias[col0 + 1];
            float2 v0 = make_float2(acc[mi][ni][0] + b0, acc[mi][ni][1] + b1);
            float2 v1 = make_float2(acc[mi][ni][2] + b0, acc[mi][ni][3] + b1);
            *(float2*)&C[row0 * N + col0]       = v0;
            *(float2*)&C[(row0 + 8) * N + col0] = v1;
        }
    }
}

__global__ __launch_bounds__(256) void gemm_proj_mma()
{
    mma_gemm_body<384>(g_sh, g_sl, g_wcath, g_wcatl, g_bcat, g_proj, 1152);
}
__global__ __launch_bounds__(256) void gemm_out_mma(const float* __restrict__ bout,
                                                    float* __restrict__ out)
{
    mma_gemm_body<960>(g_cath, g_catl, g_wouth, g_woutl, bout, out, 384);
}

// ---------------- rigid transform of qp/kvp points ----------------
__global__ __launch_bounds__(192) void transform_points(const float* __restrict__ rot,
                                                        const float* __restrict__ trans)
{
    int n = blockIdx.x;
    __shared__ float R[9], T[3];
    int t = threadIdx.x;
    if (t < 9) R[t] = rot[n * 9 + t];
    if (t < 3) T[t] = trans[n * 3 + t];
    __syncthreads();
    if (t < 48) {
        const float* base = g_proj + (size_t)n * 1152 + 576;
        float x = base[t], y = base[48 + t], z = base[96 + t];
        float* o = g_qpts + (size_t)n * 144 + t * 3;
        o[0] = fmaf(R[0], x, fmaf(R[1], y, fmaf(R[2], z, T[0])));
        o[1] = fmaf(R[3], x, fmaf(R[4], y, fmaf(R[5], z, T[1])));
        o[2] = fmaf(R[6], x, fmaf(R[7], y, fmaf(R[8], z, T[2])));
    } else {
        int j = t - 48;
        const float* base = g_proj + (size_t)n * 1152 + 720;
        float x = base[j], y = base[144 + j], z = base[288 + j];
        float* o = g_kvpts + (size_t)n * 432 + j * 3;
        o[0] = fmaf(R[0], x, fmaf(R[1], y, fmaf(R[2], z, T[0])));
        o[1] = fmaf(R[3], x, fmaf(R[4], y, fmaf(R[5], z, T[1])));
        o[2] = fmaf(R[6], x, fmaf(R[7], y, fmaf(R[8], z, T[2])));
    }
}

// ---------------- zproj v2 (reverted: measured 178us; v3 regressed) ----------------
__global__ __launch_bounds__(256) void zproj(const float* __restrict__ z,
                                             const float* __restrict__ wb,  const float* __restrict__ bb,
                                             const float* __restrict__ wdz, const float* __restrict__ bdz)
{
    __shared__ float sz[256 * 33];
    __shared__ float sw[32 * 44];
    const int tid = threadIdx.x;
    const size_t e0 = (size_t)blockIdx.x * 256;

    float acc[44];
#pragma unroll
    for (int c = 0; c < 44; c++) acc[c] = 0.f;

    for (int pass = 0; pass < 4; pass++) {
        if (pass) __syncthreads();
#pragma unroll
        for (int idx = tid; idx < 256 * 32; idx += 256) {
            int row = idx >> 5, k = idx & 31;
            sz[row * 33 + k] = z[(e0 + row) * 128 + pass * 32 + k];
        }
        for (int i = tid; i < 32 * 44; i += 256) {
            int kk = i / 44, c = i % 44;
            sw[kk * 44 + c] = (c < 12) ? wb[(pass * 32 + kk) * 12 + c]
                                       : wdz[(pass * 32 + kk) * 32 + (c - 12)];
        }
        __syncthreads();

        const float4* sw4 = (const float4*)sw;
#pragma unroll 4
        for (int k = 0; k < 32; k++) {
            float zv = sz[tid * 33 + k];
#pragma unroll
            for (int j = 0; j < 11; j++) {
                float4 w = sw4[k * 11 + j];
                acc[4 * j + 0] = fmaf(zv, w.x, acc[4 * j + 0]);
                acc[4 * j + 1] = fmaf(zv, w.y, acc[4 * j + 1]);
                acc[4 * j + 2] = fmaf(zv, w.z, acc[4 * j + 2]);
                acc[4 * j + 3] = fmaf(zv, w.w, acc[4 * j + 3]);
            }
        }
    }

    const size_t e = e0 + tid;
    const float S = 0.5773502691896258f;
    float tb[12];
#pragma unroll
    for (int c = 0; c < 12; c++) tb[c] = S * (acc[c] + __ldg(bb + c));
    float4* pb = (float4*)(g_bpair + e * 12);
#pragma unroll
    for (int i = 0; i < 3; i++)
        pb[i] = make_float4(tb[4 * i], tb[4 * i + 1], tb[4 * i + 2], tb[4 * i + 3]);
    float tz[32];
#pragma unroll
    for (int c = 0; c < 32; c++) tz[c] = acc[12 + c] + __ldg(bdz + c);
    float4* pz = (float4*)(g_pairz + e * 32);
#pragma unroll
    for (int i = 0; i < 8; i++)
        pz[i] = make_float4(tz[4 * i], tz[4 * i + 1], tz[4 * i + 2], tz[4 * i + 3]);
}

// ---------------- fused attention (writes cat as bf16 hi/lo) ----------------
__device__ __forceinline__ void put_cat(size_t n, int idx, float v)
{
    split_store(g_cath + n * 960 + idx, g_catl + n * 960 + idx, v);
}

__global__ __launch_bounds__(384) void attn_kernel(const int* __restrict__ edge_index,
                                                   const float* __restrict__ rot,
                                                   const float* __restrict__ trans,
                                                   const float* __restrict__ mask,
                                                   const float* __restrict__ head_weights)
{
    int n = blockIdx.x;
    int t = threadIdx.x;
    __shared__ int   s_idx[32];
    __shared__ float s_mask[32];
    __shared__ float s_q[192];
    __shared__ float s_qp[144];
    __shared__ float s_R[9], s_T[3];
    __shared__ float s_hw[12];
    __shared__ float s_a[12][33];
    __shared__ float s_opt[288];
    __shared__ float s_pz[32][33];

    if (t < 32) {
        int nb = edge_index[n * 32 + t];
        s_idx[t]  = nb;
        s_mask[t] = mask[nb];
    }
    if (t >= 32 && t < 224)  s_q [t - 32]  = g_proj[(size_t)n * 1152 + (t - 32)];
    if (t >= 224 && t < 368) s_qp[t - 224] = g_qpts[(size_t)n * 144 + (t - 224)];
    if (t >= 368 && t < 377) s_R [t - 368] = rot  [n * 9 + (t - 368)];
    if (t >= 377 && t < 380) s_T [t - 377] = trans[n * 3 + (t - 377)];
    if (t < 12) {
        float x = head_weights[t];
        float sp = (x > 20.f) ? x : log1pf(expf(x));
        s_hw[t] = sp * 0.13608276348795434f;   // softplus * sqrt(1/54)
    }
    __syncthreads();

    {
        int h = t >> 5, k = t & 31;
        int nb = s_idx[k];
        const float* kg = g_proj + (size_t)nb * 1152 + 192 + h * 32;
        float dot = 0.f;
#pragma unroll
        for (int c = 0; c < 16; c++) dot = fmaf(s_q[h * 16 + c], kg[c], dot);
        const float* kp = g_kvpts + (size_t)nb * 432 + h * 36;
        float pt = 0.f;
#pragma unroll
        for (int pi = 0; pi < 12; pi++) {
            float d = s_qp[h * 12 + pi] - kp[pi];
            pt = fmaf(d, d, pt);
        }
        float logit = dot * 0.14433756729740643f
                    + g_bpair[((size_t)n * 32 + k) * 12 + h]
                    - 0.5f * s_hw[h] * pt
                    + 100000.0f * (s_mask[k] - 1.0f);
        float m = logit;
#pragma unroll
        for (int o = 16; o; o >>= 1) m = fmaxf(m, __shfl_xor_sync(0xffffffffu, m, o));
        float e = expf(logit - m);
        float ssum = e;
#pragma unroll
        for (int o = 16; o; o >>= 1) ssum += __shfl_xor_sync(0xffffffffu, ssum, o);
        s_a[h][k] = e / ssum;
    }
    for (int i = t; i < 32 * 32; i += 384)
        s_pz[i >> 5][i & 31] = g_pairz[((size_t)n * 32 + (i >> 5)) * 32 + (i & 31)];
    __syncthreads();

    if (t < 192) {
        int h = t >> 4, c = t & 15;
        float acc = 0.f;
#pragma unroll 4
        for (int k = 0; k < 32; k++)
            acc = fmaf(s_a[h][k], g_proj[(size_t)s_idx[k] * 1152 + 192 + h * 32 + 16 + c], acc);
        put_cat(n, h * 16 + c, acc);
    }
    if (t < 288) {
        int j = t / 3, i = t - j * 3;
        int h = j >> 3, p = j & 7;
        float acc = 0.f;
#pragma unroll 4
        for (int k = 0; k < 32; k++)
            acc = fmaf(s_a[h][k], g_kvpts[(size_t)s_idx[k] * 432 + h * 36 + (4 + p) * 3 + i], acc);
        s_opt[t] = acc;
    }
    {
        int h = t >> 5, c = t & 31;
        float acc = 0.f;
#pragma unroll
        for (int k = 0; k < 32; k++)
            acc = fmaf(s_a[h][k], s_pz[k][c], acc);
        put_cat(n, 576 + h * 32 + c, acc);
    }
    __syncthreads();
    if (t < 96) {
        float gx = s_opt[t * 3 + 0] - s_T[0];
        float gy = s_opt[t * 3 + 1] - s_T[1];
        float gz = s_opt[t * 3 + 2] - s_T[2];
        float lx = fmaf(s_R[0], gx, fmaf(s_R[3], gy, s_R[6] * gz));
        float ly = fmaf(s_R[1], gx, fmaf(s_R[4], gy, s_R[7] * gz));
        float lz = fmaf(s_R[2], gx, fmaf(s_R[5], gy, s_R[8] * gz));
        put_cat(n, 192 + t, lx);
        put_cat(n, 288 + t, ly);
        put_cat(n, 384 + t, lz);
        put_cat(n, 480 + t, sqrtf(fmaf(lx, lx, fmaf(ly, ly, fmaf(lz, lz, 1e-8f)))));
    }
}

// ---------------- launch (gemm_proj_mma in profile slot 4) ----------------
extern "C" void kernel_launch(void* const* d_in, const int* in_sizes, int n_in,
                              void* d_out, int out_size)
{
    const float* s     = (const float*)d_in[0];
    const float* z     = (const float*)d_in[1];
    const int*   ei    = (const int*)  d_in[2];
    const float* rot   = (const float*)d_in[3];
    const float* trans = (const float*)d_in[4];
    const float* mask  = (const float*)d_in[5];
    const float* w_q   = (const float*)d_in[6];
    const float* b_q   = (const float*)d_in[7];
    const float* w_kv  = (const float*)d_in[8];
    const float* b_kv  = (const float*)d_in[9];
    const float* w_qp  = (const float*)d_in[10];
    const float* b_qp  = (const float*)d_in[11];
    const float* w_kvp = (const float*)d_in[12];
    const float* b_kvp = (const float*)d_in[13];
    const float* w_b   = (const float*)d_in[14];
    const float* b_b   = (const float*)d_in[15];
    const float* w_dz  = (const float*)d_in[16];
    const float* b_dz  = (const float*)d_in[17];
    const float* hw    = (const float*)d_in[18];
    const float* w_out = (const float*)d_in[19];
    const float* b_out = (const float*)d_in[20];
    float* out = (float*)d_out;

    cvt_s<<<(NNODES * 384 / 4) / 256, 256>>>((const float4*)s);            // slot 1
    pack_w<<<256, 256>>>(w_q, w_kv, w_qp, w_kvp);                          // slot 2
    prep_small<<<(960 * 384 + 255) / 256, 256>>>(b_q, b_kv, b_qp, b_kvp, w_out); // slot 3
    gemm_proj_mma<<<dim3(1152 / BN, NNODES / BM), 256>>>();                // slot 4 (profiled)
    transform_points<<<NNODES, 192>>>(rot, trans);                         // slot 5
    zproj<<<(NNODES * KNBR) / 256, 256>>>(z, w_b, b_b, w_dz, b_dz);        // slot 6
    attn_kernel<<<NNODES, 384>>>(ei, rot, trans, mask, hw);                // slot 7
    gemm_out_mma<<<dim3(384 / BN, NNODES / BM), 256>>>(b_out, out);        // slot 8
}

// round 8
// speedup vs baseline: 2.1566x; 1.2025x over previous
#include <cuda_runtime.h>
#include <cuda_bf16.h>
#include <math.h>

#define NNODES 8192
#define KNBR   32

// ---------------- scratch (static device arrays; no allocation) ----------------
__device__ __align__(16) float g_proj [NNODES * 1152];   // q(192)|kv(384)|qp(144)|kvp(432)
__device__ __align__(16) float g_bcat [1152];
__device__ __align__(16) float g_qpts [NNODES * 144];
__device__ __align__(16) float g_kvpts[NNODES * 432];
__device__ __align__(16) float g_bpair[NNODES * KNBR * 12];
__device__ __align__(16) float g_pairz[NNODES * KNBR * 32];
// bf16 hi/lo split operands for tensor-core GEMMs
__device__ __align__(16) __nv_bfloat16 g_sh   [NNODES * 384];
__device__ __align__(16) __nv_bfloat16 g_sl   [NNODES * 384];
__device__ __align__(16) __nv_bfloat16 g_wcath[384 * 1152];
__device__ __align__(16) __nv_bfloat16 g_wcatl[384 * 1152];
__device__ __align__(16) __nv_bfloat16 g_wouth[960 * 384];
__device__ __align__(16) __nv_bfloat16 g_woutl[960 * 384];
__device__ __align__(16) __nv_bfloat16 g_cath [NNODES * 960];
__device__ __align__(16) __nv_bfloat16 g_catl [NNODES * 960];
__device__ __align__(16) __nv_bfloat16 g_zwh  [128 * 64];   // zproj weights packed [K=128, N=64]
__device__ __align__(16) __nv_bfloat16 g_zwl  [128 * 64];

// ---------------- helpers ----------------
__device__ __forceinline__ void split_store(__nv_bfloat16* ph, __nv_bfloat16* pl, float x)
{
    __nv_bfloat16 h = __float2bfloat16(x);
    *ph = h;
    *pl = __float2bfloat16(x - __bfloat162float(h));
}

__device__ __forceinline__ void mma_bf16(float* c, const unsigned* a, const unsigned* b)
{
    asm volatile(
        "mma.sync.aligned.m16n8k16.row.col.f32.bf16.bf16.f32 "
        "{%0,%1,%2,%3}, {%4,%5,%6,%7}, {%8,%9}, {%0,%1,%2,%3};"
        : "+f"(c[0]), "+f"(c[1]), "+f"(c[2]), "+f"(c[3])
        : "r"(a[0]), "r"(a[1]), "r"(a[2]), "r"(a[3]), "r"(b[0]), "r"(b[1]));
}
__device__ __forceinline__ void ldsm_x4(unsigned* d, unsigned addr)
{
    asm volatile("ldmatrix.sync.aligned.m8n8.x4.shared.b16 {%0,%1,%2,%3}, [%4];"
                 : "=r"(d[0]), "=r"(d[1]), "=r"(d[2]), "=r"(d[3]) : "r"(addr));
}
__device__ __forceinline__ void ldsm_x2t(unsigned* d, unsigned addr)
{
    asm volatile("ldmatrix.sync.aligned.m8n8.x2.trans.shared.b16 {%0,%1}, [%2];"
                 : "=r"(d[0]), "=r"(d[1]) : "r"(addr));
}

// ---------------- converters / packers ----------------
__global__ void cvt_s(const float4* __restrict__ s)   // grid covers NNODES*384/4
{
    int i = blockIdx.x * blockDim.x + threadIdx.x;
    float4 v = s[i];
    __nv_bfloat16* ph = g_sh + i * 4;
    __nv_bfloat16* pl = g_sl + i * 4;
    split_store(ph + 0, pl + 0, v.x);
    split_store(ph + 1, pl + 1, v.y);
    split_store(ph + 2, pl + 2, v.z);
    split_store(ph + 3, pl + 3, v.w);
}

__global__ void pack_w(const float* __restrict__ wq, const float* __restrict__ wkv,
                       const float* __restrict__ wqp, const float* __restrict__ wkvp)
{
    int t = blockIdx.x * blockDim.x + threadIdx.x;
    int stride = gridDim.x * blockDim.x;
    for (int i = t; i < 384 * 1152; i += stride) {
        int r = i / 1152, c = i % 1152;
        float v;
        if      (c < 192) v = wq  [r * 192 + c];
        else if (c < 576) v = wkv [r * 384 + (c - 192)];
        else if (c < 720) v = wqp [r * 144 + (c - 576)];
        else              v = wkvp[r * 432 + (c - 720)];
        split_store(g_wcath + i, g_wcatl + i, v);
    }
}

__global__ void prep_small(const float* __restrict__ bq, const float* __restrict__ bkv,
                           const float* __restrict__ bqp, const float* __restrict__ bkvp,
                           const float* __restrict__ wout,
                           const float* __restrict__ wb, const float* __restrict__ wdz)
{
    int i = blockIdx.x * blockDim.x + threadIdx.x;
    if (i < 1152) {
        float v;
        if      (i < 192) v = bq [i];
        else if (i < 576) v = bkv[i - 192];
        else if (i < 720) v = bqp[i - 576];
        else              v = bkvp[i - 720];
        g_bcat[i] = v;
    }
    if (i < 960 * 384)
        split_store(g_wouth + i, g_woutl + i, wout[i]);
    if (i < 128 * 64) {            // zproj weight pack: [k, n]; n<12 wb, 12..43 wdz, else 0
        int r = i >> 6, c = i & 63;
        float v = 0.f;
        if      (c < 12) v = wb [r * 12 + c];
        else if (c < 44) v = wdz[r * 32 + (c - 12)];
        split_store(g_zwh + i, g_zwl + i, v);
    }
}

// ---------------- bf16 hi/lo compensated tensor-core GEMM ----------------
#define BM 128
#define BN 64
#define KC 32
template<int K>
__device__ __forceinline__ void mma_gemm_body(
    const __nv_bfloat16* __restrict__ Ah, const __nv_bfloat16* __restrict__ Al,
    const __nv_bfloat16* __restrict__ Bh, const __nv_bfloat16* __restrict__ Bl,
    const float* __restrict__ bias, float* __restrict__ C, const int N)
{
    __shared__ __nv_bfloat16 sAh[BM * 40], sAl[BM * 40];
    __shared__ __nv_bfloat16 sBh[KC * 72], sBl[KC * 72];

    const int tid  = threadIdx.x;
    const int lane = tid & 31, warp = tid >> 5;
    const int wm = warp >> 2, wn = warp & 3;
    const long brow = (long)blockIdx.y * BM;
    const long bcol = (long)blockIdx.x * BN;

    float acc[4][2][4];
#pragma unroll
    for (int mi = 0; mi < 4; mi++)
#pragma unroll
        for (int ni = 0; ni < 2; ni++)
#pragma unroll
            for (int r = 0; r < 4; r++) acc[mi][ni][r] = 0.f;

    const int arow  = tid >> 1, apart = (tid & 1) * 16;
    const int bkr   = tid >> 3, bnp   = (tid & 7) * 8;

    const unsigned sAh_u = (unsigned)__cvta_generic_to_shared(sAh);
    const unsigned sAl_u = (unsigned)__cvta_generic_to_shared(sAl);
    const unsigned sBh_u = (unsigned)__cvta_generic_to_shared(sBh);
    const unsigned sBl_u = (unsigned)__cvta_generic_to_shared(sBl);

    uint4 rah0, rah1, ral0, ral1, rbh, rbl;
    {
        const size_t aoff = (size_t)(brow + arow) * K + apart;
        rah0 = *(const uint4*)(Ah + aoff); rah1 = *(const uint4*)(Ah + aoff + 8);
        ral0 = *(const uint4*)(Al + aoff); ral1 = *(const uint4*)(Al + aoff + 8);
        const size_t boff = (size_t)bkr * N + bcol + bnp;
        rbh = *(const uint4*)(Bh + boff);
        rbl = *(const uint4*)(Bl + boff);
    }

    for (int kc = 0; kc < K; kc += KC) {
        *(uint4*)(sAh + arow * 40 + apart)     = rah0;
        *(uint4*)(sAh + arow * 40 + apart + 8) = rah1;
        *(uint4*)(sAl + arow * 40 + apart)     = ral0;
        *(uint4*)(sAl + arow * 40 + apart + 8) = ral1;
        *(uint4*)(sBh + bkr * 72 + bnp) = rbh;
        *(uint4*)(sBl + bkr * 72 + bnp) = rbl;
        __syncthreads();

        const bool more = (kc + KC) < K;
        if (more) {
            const size_t aoff = (size_t)(brow + arow) * K + kc + KC + apart;
            rah0 = *(const uint4*)(Ah + aoff); rah1 = *(const uint4*)(Ah + aoff + 8);
            ral0 = *(const uint4*)(Al + aoff); ral1 = *(const uint4*)(Al + aoff + 8);
            const size_t boff = (size_t)(kc + KC + bkr) * N + bcol + bnp;
            rbh = *(const uint4*)(Bh + boff);
            rbl = *(const uint4*)(Bl + boff);
        }

#pragma unroll
        for (int ks = 0; ks < 2; ks++) {
            const int kk = ks * 16;
            unsigned afh[4][4], afl[4][4];
            const int g = lane >> 3, r = lane & 7;
#pragma unroll
            for (int mi = 0; mi < 4; mi++) {
                const int row = wm * 64 + mi * 16 + (g & 1) * 8 + r;
                const int col = kk + (g >> 1) * 8;
                ldsm_x4(afh[mi], sAh_u + (unsigned)(row * 40 + col) * 2u);
                ldsm_x4(afl[mi], sAl_u + (unsigned)(row * 40 + col) * 2u);
            }
            unsigned bfh[2][2], bfl[2][2];
            const int g2 = (lane >> 3) & 1, r2 = lane & 7;
#pragma unroll
            for (int ni = 0; ni < 2; ni++) {
                const int krow = kk + g2 * 8 + r2;
                const int col  = wn * 16 + ni * 8;
                ldsm_x2t(bfh[ni], sBh_u + (unsigned)(krow * 72 + col) * 2u);
                ldsm_x2t(bfl[ni], sBl_u + (unsigned)(krow * 72 + col) * 2u);
            }
#pragma unroll
            for (int mi = 0; mi < 4; mi++)
#pragma unroll
                for (int ni = 0; ni < 2; ni++) {
                    mma_bf16(acc[mi][ni], afh[mi], bfh[ni]);
                    mma_bf16(acc[mi][ni], afh[mi], bfl[ni]);
                    mma_bf16(acc[mi][ni], afl[mi], bfh[ni]);
                }
        }
        if (more) __syncthreads();
    }

    const int gr = lane >> 2, gc = (lane & 3) * 2;
#pragma unroll
    for (int mi = 0; mi < 4; mi++) {
        const long row0 = brow + wm * 64 + mi * 16 + gr;
#pragma unroll
        for (int ni = 0; ni < 2; ni++) {
            const long col0 = bcol + wn * 16 + ni * 8 + gc;
            const float b0 = bias[col0], b1 = bias[col0 + 1];
            float2 v0 = make_float2(acc[mi][ni][0] + b0, acc[mi][ni][1] + b1);
            float2 v1 = make_float2(acc[mi][ni][2] + b0, acc[mi][ni][3] + b1);
            *(float2*)&C[row0 * N + col0]       = v0;
            *(float2*)&C[(row0 + 8) * N + col0] = v1;
        }
    }
}

__global__ __launch_bounds__(256) void gemm_proj_mma()
{
    mma_gemm_body<384>(g_sh, g_sl, g_wcath, g_wcatl, g_bcat, g_proj, 1152);
}
__global__ __launch_bounds__(256) void gemm_out_mma(const float* __restrict__ bout,
                                                    float* __restrict__ out)
{
    mma_gemm_body<960>(g_cath, g_catl, g_wouth, g_woutl, bout, out, 384);
}

// ---------------- zproj via tensor cores: fused fp32->bf16 hi/lo conversion ----------------
// A = z [E=262144, K=128] fp32 (converted in-kernel), B = g_zwh/g_zwl [128, 64].
// Block: 128 edges, full N=64, KC=32 (4 chunks). Epilogue routes cols to bpair/pairz.
__global__ __launch_bounds__(256) void zproj_mma(const float* __restrict__ z,
                                                 const float* __restrict__ bb,
                                                 const float* __restrict__ bdz)
{
    __shared__ __nv_bfloat16 sAh[BM * 40], sAl[BM * 40];
    __shared__ __nv_bfloat16 sBh[KC * 72], sBl[KC * 72];

    const int tid  = threadIdx.x;
    const int lane = tid & 31, warp = tid >> 5;
    const int wm = warp >> 2, wn = warp & 3;
    const long brow = (long)blockIdx.x * BM;   // edge base

    float acc[4][2][4];
#pragma unroll
    for (int mi = 0; mi < 4; mi++)
#pragma unroll
        for (int ni = 0; ni < 2; ni++)
#pragma unroll
            for (int r = 0; r < 4; r++) acc[mi][ni][r] = 0.f;

    const int arow  = tid >> 1, apart = (tid & 1) * 16;    // 16 fp32 per thread per chunk
    const int bkr   = tid >> 3, bnp   = (tid & 7) * 8;

    const unsigned sAh_u = (unsigned)__cvta_generic_to_shared(sAh);
    const unsigned sAl_u = (unsigned)__cvta_generic_to_shared(sAl);
    const unsigned sBh_u = (unsigned)__cvta_generic_to_shared(sBh);
    const unsigned sBl_u = (unsigned)__cvta_generic_to_shared(sBl);

    // prologue: stage chunk 0
    float4 ra[4];
    uint4 rbh, rbl;
    {
        const float* ap = z + (size_t)(brow + arow) * 128 + apart;
#pragma unroll
        for (int j = 0; j < 4; j++) ra[j] = *(const float4*)(ap + j * 4);
        rbh = *(const uint4*)(g_zwh + bkr * 64 + bnp);
        rbl = *(const uint4*)(g_zwl + bkr * 64 + bnp);
    }

    for (int kc = 0; kc < 128; kc += KC) {
        // convert + commit A, commit B
        __nv_bfloat16 hh[16], ll[16];
#pragma unroll
        for (int j = 0; j < 4; j++) {
            float v[4] = {ra[j].x, ra[j].y, ra[j].z, ra[j].w};
#pragma unroll
            for (int q = 0; q < 4; q++) {
                __nv_bfloat16 h = __float2bfloat16(v[q]);
                hh[j * 4 + q] = h;
                ll[j * 4 + q] = __float2bfloat16(v[q] - __bfloat162float(h));
            }
        }
        *(uint4*)(sAh + arow * 40 + apart)     = *(uint4*)hh;
        *(uint4*)(sAh + arow * 40 + apart + 8) = *(uint4*)(hh + 8);
        *(uint4*)(sAl + arow * 40 + apart)     = *(uint4*)ll;
        *(uint4*)(sAl + arow * 40 + apart + 8) = *(uint4*)(ll + 8);
        *(uint4*)(sBh + bkr * 72 + bnp) = rbh;
        *(uint4*)(sBl + bkr * 72 + bnp) = rbl;
        __syncthreads();

        const bool more = (kc + KC) < 128;
        if (more) {
            const float* ap = z + (size_t)(brow + arow) * 128 + kc + KC + apart;
#pragma unroll
            for (int j = 0; j < 4; j++) ra[j] = *(const float4*)(ap + j * 4);
            rbh = *(const uint4*)(g_zwh + (kc + KC + bkr) * 64 + bnp);
            rbl = *(const uint4*)(g_zwl + (kc + KC + bkr) * 64 + bnp);
        }

#pragma unroll
        for (int ks = 0; ks < 2; ks++) {
            const int kk = ks * 16;
            unsigned afh[4][4], afl[4][4];
            const int g = lane >> 3, r = lane & 7;
#pragma unroll
            for (int mi = 0; mi < 4; mi++) {
                const int row = wm * 64 + mi * 16 + (g & 1) * 8 + r;
                const int col = kk + (g >> 1) * 8;
                ldsm_x4(afh[mi], sAh_u + (unsigned)(row * 40 + col) * 2u);
                ldsm_x4(afl[mi], sAl_u + (unsigned)(row * 40 + col) * 2u);
            }
            unsigned bfh[2][2], bfl[2][2];
            const int g2 = (lane >> 3) & 1, r2 = lane & 7;
#pragma unroll
            for (int ni = 0; ni < 2; ni++) {
                const int krow = kk + g2 * 8 + r2;
                const int col  = wn * 16 + ni * 8;
                ldsm_x2t(bfh[ni], sBh_u + (unsigned)(krow * 72 + col) * 2u);
                ldsm_x2t(bfl[ni], sBl_u + (unsigned)(krow * 72 + col) * 2u);
            }
#pragma unroll
            for (int mi = 0; mi < 4; mi++)
#pragma unroll
                for (int ni = 0; ni < 2; ni++) {
                    mma_bf16(acc[mi][ni], afh[mi], bfh[ni]);
                    mma_bf16(acc[mi][ni], afh[mi], bfl[ni]);
                    mma_bf16(acc[mi][ni], afl[mi], bfh[ni]);
                }
        }
        if (more) __syncthreads();
    }

    // epilogue: col<12 -> bpair (scaled), 12..43 -> pairz, >=44 dropped
    const float S = 0.5773502691896258f;  // sqrt(1/3)
    const int gr = lane >> 2, gc = (lane & 3) * 2;
#pragma unroll
    for (int mi = 0; mi < 4; mi++) {
        const long e0 = brow + wm * 64 + mi * 16 + gr;
#pragma unroll
        for (int ni = 0; ni < 2; ni++) {
            const int colb = wn * 16 + ni * 8 + gc;
#pragma unroll
            for (int r = 0; r < 4; r++) {
                const long e   = e0 + (r >> 1) * 8;
                const int  col = colb + (r & 1);
                const float v = acc[mi][ni][r];
                if (col < 12)
                    g_bpair[e * 12 + col] = S * (v + __ldg(bb + col));
                else if (col < 44)
                    g_pairz[e * 32 + (col - 12)] = v + __ldg(bdz + (col - 12));
            }
        }
    }
}

// ---------------- rigid transform of qp/kvp points ----------------
__global__ __launch_bounds__(192) void transform_points(const float* __restrict__ rot,
                                                        const float* __restrict__ trans)
{
    int n = blockIdx.x;
    __shared__ float R[9], T[3];
    int t = threadIdx.x;
    if (t < 9) R[t] = rot[n * 9 + t];
    if (t < 3) T[t] = trans[n * 3 + t];
    __syncthreads();
    if (t < 48) {
        const float* base = g_proj + (size_t)n * 1152 + 576;
        float x = base[t], y = base[48 + t], z = base[96 + t];
        float* o = g_qpts + (size_t)n * 144 + t * 3;
        o[0] = fmaf(R[0], x, fmaf(R[1], y, fmaf(R[2], z, T[0])));
        o[1] = fmaf(R[3], x, fmaf(R[4], y, fmaf(R[5], z, T[1])));
        o[2] = fmaf(R[6], x, fmaf(R[7], y, fmaf(R[8], z, T[2])));
    } else {
        int j = t - 48;
        const float* base = g_proj + (size_t)n * 1152 + 720;
        float x = base[j], y = base[144 + j], z = base[288 + j];
        float* o = g_kvpts + (size_t)n * 432 + j * 3;
        o[0] = fmaf(R[0], x, fmaf(R[1], y, fmaf(R[2], z, T[0])));
        o[1] = fmaf(R[3], x, fmaf(R[4], y, fmaf(R[5], z, T[1])));
        o[2] = fmaf(R[6], x, fmaf(R[7], y, fmaf(R[8], z, T[2])));
    }
}

// ---------------- fused attention (writes cat as bf16 hi/lo) ----------------
__device__ __forceinline__ void put_cat(size_t n, int idx, float v)
{
    split_store(g_cath + n * 960 + idx, g_catl + n * 960 + idx, v);
}

__global__ __launch_bounds__(384) void attn_kernel(const int* __restrict__ edge_index,
                                                   const float* __restrict__ rot,
                                                   const float* __restrict__ trans,
                                                   const float* __restrict__ mask,
                                                   const float* __restrict__ head_weights)
{
    int n = blockIdx.x;
    int t = threadIdx.x;
    __shared__ int   s_idx[32];
    __shared__ float s_mask[32];
    __shared__ float s_q[192];
    __shared__ float s_qp[144];
    __shared__ float s_R[9], s_T[3];
    __shared__ float s_hw[12];
    __shared__ float s_a[12][33];
    __shared__ float s_opt[288];
    __shared__ float s_pz[32][33];

    if (t < 32) {
        int nb = edge_index[n * 32 + t];
        s_idx[t]  = nb;
        s_mask[t] = mask[nb];
    }
    if (t >= 32 && t < 224)  s_q [t - 32]  = g_proj[(size_t)n * 1152 + (t - 32)];
    if (t >= 224 && t < 368) s_qp[t - 224] = g_qpts[(size_t)n * 144 + (t - 224)];
    if (t >= 368 && t < 377) s_R [t - 368] = rot  [n * 9 + (t - 368)];
    if (t >= 377 && t < 380) s_T [t - 377] = trans[n * 3 + (t - 377)];
    if (t < 12) {
        float x = head_weights[t];
        float sp = (x > 20.f) ? x : log1pf(expf(x));
        s_hw[t] = sp * 0.13608276348795434f;   // softplus * sqrt(1/54)
    }
    __syncthreads();

    {
        int h = t >> 5, k = t & 31;
        int nb = s_idx[k];
        const float* kg = g_proj + (size_t)nb * 1152 + 192 + h * 32;
        float dot = 0.f;
#pragma unroll
        for (int c = 0; c < 16; c++) dot = fmaf(s_q[h * 16 + c], kg[c], dot);
        const float* kp = g_kvpts + (size_t)nb * 432 + h * 36;
        float pt = 0.f;
#pragma unroll
        for (int pi = 0; pi < 12; pi++) {
            float d = s_qp[h * 12 + pi] - kp[pi];
            pt = fmaf(d, d, pt);
        }
        float logit = dot * 0.14433756729740643f
                    + g_bpair[((size_t)n * 32 + k) * 12 + h]
                    - 0.5f * s_hw[h] * pt
                    + 100000.0f * (s_mask[k] - 1.0f);
        float m = logit;
#pragma unroll
        for (int o = 16; o; o >>= 1) m = fmaxf(m, __shfl_xor_sync(0xffffffffu, m, o));
        float e = expf(logit - m);
        float ssum = e;
#pragma unroll
        for (int o = 16; o; o >>= 1) ssum += __shfl_xor_sync(0xffffffffu, ssum, o);
        s_a[h][k] = e / ssum;
    }
    for (int i = t; i < 32 * 32; i += 384)
        s_pz[i >> 5][i & 31] = g_pairz[((size_t)n * 32 + (i >> 5)) * 32 + (i & 31)];
    __syncthreads();

    if (t < 192) {
        int h = t >> 4, c = t & 15;
        float acc = 0.f;
#pragma unroll 4
        for (int k = 0; k < 32; k++)
            acc = fmaf(s_a[h][k], g_proj[(size_t)s_idx[k] * 1152 + 192 + h * 32 + 16 + c], acc);
        put_cat(n, h * 16 + c, acc);
    }
    if (t < 288) {
        int j = t / 3, i = t - j * 3;
        int h = j >> 3, p = j & 7;
        float acc = 0.f;
#pragma unroll 4
        for (int k = 0; k < 32; k++)
            acc = fmaf(s_a[h][k], g_kvpts[(size_t)s_idx[k] * 432 + h * 36 + (4 + p) * 3 + i], acc);
        s_opt[t] = acc;
    }
    {
        int h = t >> 5, c = t & 31;
        float acc = 0.f;
#pragma unroll
        for (int k = 0; k < 32; k++)
            acc = fmaf(s_a[h][k], s_pz[k][c], acc);
        put_cat(n, 576 + h * 32 + c, acc);
    }
    __syncthreads();
    if (t < 96) {
        float gx = s_opt[t * 3 + 0] - s_T[0];
        float gy = s_opt[t * 3 + 1] - s_T[1];
        float gz = s_opt[t * 3 + 2] - s_T[2];
        float lx = fmaf(s_R[0], gx, fmaf(s_R[3], gy, s_R[6] * gz));
        float ly = fmaf(s_R[1], gx, fmaf(s_R[4], gy, s_R[7] * gz));
        float lz = fmaf(s_R[2], gx, fmaf(s_R[5], gy, s_R[8] * gz));
        put_cat(n, 192 + t, lx);
        put_cat(n, 288 + t, ly);
        put_cat(n, 384 + t, lz);
        put_cat(n, 480 + t, sqrtf(fmaf(lx, lx, fmaf(ly, ly, fmaf(lz, lz, 1e-8f)))));
    }
}

// ---------------- launch (zproj_mma in profile slot 4) ----------------
extern "C" void kernel_launch(void* const* d_in, const int* in_sizes, int n_in,
                              void* d_out, int out_size)
{
    const float* s     = (const float*)d_in[0];
    const float* z     = (const float*)d_in[1];
    const int*   ei    = (const int*)  d_in[2];
    const float* rot   = (const float*)d_in[3];
    const float* trans = (const float*)d_in[4];
    const float* mask  = (const float*)d_in[5];
    const float* w_q   = (const float*)d_in[6];
    const float* b_q   = (const float*)d_in[7];
    const float* w_kv  = (const float*)d_in[8];
    const float* b_kv  = (const float*)d_in[9];
    const float* w_qp  = (const float*)d_in[10];
    const float* b_qp  = (const float*)d_in[11];
    const float* w_kvp = (const float*)d_in[12];
    const float* b_kvp = (const float*)d_in[13];
    const float* w_b   = (const float*)d_in[14];
    const float* b_b   = (const float*)d_in[15];
    const float* w_dz  = (const float*)d_in[16];
    const float* b_dz  = (const float*)d_in[17];
    const float* hw    = (const float*)d_in[18];
    const float* w_out = (const float*)d_in[19];
    const float* b_out = (const float*)d_in[20];
    float* out = (float*)d_out;

    cvt_s<<<(NNODES * 384 / 4) / 256, 256>>>((const float4*)s);                        // slot 1
    pack_w<<<256, 256>>>(w_q, w_kv, w_qp, w_kvp);                                      // slot 2
    prep_small<<<(960 * 384 + 255) / 256, 256>>>(b_q, b_kv, b_qp, b_kvp, w_out, w_b, w_dz); // slot 3
    zproj_mma<<<(NNODES * KNBR) / BM, 256>>>(z, b_b, b_dz);                            // slot 4 (profiled)
    gemm_proj_mma<<<dim3(1152 / BN, NNODES / BM), 256>>>();                            // slot 5
    transform_points<<<NNODES, 192>>>(rot, trans);                                     // slot 6
    attn_kernel<<<NNODES, 384>>>(ei, rot, trans, mask, hw);                            // slot 7
    gemm_out_mma<<<dim3(384 / BN, NNODES / BM), 256>>>(b_out, out);                    // slot 8
}